// round 1
// baseline (speedup 1.0000x reference)
#include <cuda_runtime.h>
#include <cuda_bf16.h>
#include <cstdint>

#define N_NODES 50000
#define D 128
#define BM 64
#define GEMM_THREADS 256

// Scratch for y = x @ W^T  (25.6 MB) — __device__ global, no allocation.
__device__ float g_y[(size_t)N_NODES * D];

// ---------------------------------------------------------------------------
// Kernel 1: y = x @ W^T.  BM=64 rows/block, full N=128, full K=128 in smem.
// Ws stored k-major (Ws[k][j]) so inner-loop W reads are consecutive-bank;
// A reads are warp-uniform (broadcast). Dynamic smem: 64*128*4 + 128*132*4 B.
// ---------------------------------------------------------------------------
__global__ void gemm_xwT(const float* __restrict__ x, const float* __restrict__ W,
                         float* __restrict__ y, int n) {
    extern __shared__ float smem[];
    float* As = smem;                 // [BM][128]
    float* Ws = smem + BM * D;        // [128][132] (pad 132 for bank spread)
    const int WS_LD = 132;

    int tid = threadIdx.x;
    int row0 = blockIdx.x * BM;

    // Load W [j][k] row-major, store transposed Ws[k][j]. One-time cost.
    for (int i = tid; i < (D * D) / 4; i += GEMM_THREADS) {
        int idx = i * 4;
        int j = idx >> 7;        // D=128
        int k = idx & 127;
        float4 v = ((const float4*)W)[i];
        Ws[(k + 0) * WS_LD + j] = v.x;
        Ws[(k + 1) * WS_LD + j] = v.y;
        Ws[(k + 2) * WS_LD + j] = v.z;
        Ws[(k + 3) * WS_LD + j] = v.w;
    }
    // Load A tile [BM][128] coalesced.
    for (int i = tid; i < (BM * D) / 4; i += GEMM_THREADS) {
        int idx = i * 4;
        int r = idx >> 7;
        int k = idx & 127;
        int gr = row0 + r;
        float4 v = (gr < n) ? ((const float4*)(x + (size_t)gr * D))[k >> 2]
                            : make_float4(0.f, 0.f, 0.f, 0.f);
        *(float4*)&As[r * D + k] = v;
    }
    __syncthreads();

    int n_idx = tid & 31;        // 32 groups of 4 output cols
    int m_idx = tid >> 5;        // 8 groups of 8 rows
    int j0 = n_idx * 4;

    float acc[8][4];
    #pragma unroll
    for (int r = 0; r < 8; r++)
        #pragma unroll
        for (int c = 0; c < 4; c++) acc[r][c] = 0.f;

    #pragma unroll 8
    for (int k = 0; k < D; k += 4) {
        float4 wv[4];
        #pragma unroll
        for (int kk = 0; kk < 4; kk++)
            wv[kk] = *(const float4*)&Ws[(k + kk) * WS_LD + j0];
        #pragma unroll
        for (int r = 0; r < 8; r++) {
            float4 av = *(const float4*)&As[(m_idx * 8 + r) * D + k];
            float a0 = av.x, a1 = av.y, a2 = av.z, a3 = av.w;
            acc[r][0] += a0 * wv[0].x + a1 * wv[1].x + a2 * wv[2].x + a3 * wv[3].x;
            acc[r][1] += a0 * wv[0].y + a1 * wv[1].y + a2 * wv[2].y + a3 * wv[3].y;
            acc[r][2] += a0 * wv[0].z + a1 * wv[1].z + a2 * wv[2].z + a3 * wv[3].z;
            acc[r][3] += a0 * wv[0].w + a1 * wv[1].w + a2 * wv[2].w + a3 * wv[3].w;
        }
    }

    #pragma unroll
    for (int r = 0; r < 8; r++) {
        int gr = row0 + m_idx * 8 + r;
        if (gr < n) {
            float4 v = make_float4(acc[r][0], acc[r][1], acc[r][2], acc[r][3]);
            *(float4*)(y + (size_t)gr * D + j0) = v;
        }
    }
}

// ---------------------------------------------------------------------------
// Kernel 2: out[i][:] = b  (broadcast bias; also un-poisons d_out).
// ---------------------------------------------------------------------------
__global__ void init_bias(float* __restrict__ out, const float* __restrict__ b,
                          int total4) {
    int i = blockIdx.x * blockDim.x + threadIdx.x;
    if (i < total4) {
        float4 bv = ((const float4*)b)[i & 31];   // 32 float4 per 128-wide row
        ((float4*)out)[i] = bv;
    }
}

// ---------------------------------------------------------------------------
// Kernel 3: edge scatter. One warp per edge: lane l handles floats [4l,4l+3].
// Gather y[col] (L2-resident), scale by w, vector-reduce into out[row].
// ---------------------------------------------------------------------------
__global__ void edge_scatter(const float* __restrict__ y,
                             const int* __restrict__ erow,
                             const int* __restrict__ ecol,
                             const float* __restrict__ ew,
                             float* __restrict__ out, int E) {
    int warp = (blockIdx.x * blockDim.x + threadIdx.x) >> 5;
    int lane = threadIdx.x & 31;
    if (warp >= E) return;

    int r = __ldg(erow + warp);
    int c = __ldg(ecol + warp);
    float w = __ldg(ew + warp);

    float4 v = ((const float4*)(y + (size_t)c * D))[lane];
    v.x *= w; v.y *= w; v.z *= w; v.w *= w;

    float* dst = out + (size_t)r * D + lane * 4;
    asm volatile("red.global.add.v4.f32 [%0], {%1, %2, %3, %4};"
                 :: "l"(dst), "f"(v.x), "f"(v.y), "f"(v.z), "f"(v.w)
                 : "memory");
}

// ---------------------------------------------------------------------------
extern "C" void kernel_launch(void* const* d_in, const int* in_sizes, int n_in,
                              void* d_out, int out_size) {
    const float* x    = (const float*)d_in[0];
    const int*   erow = (const int*)d_in[1];
    const int*   ecol = (const int*)d_in[2];
    const float* ew   = (const float*)d_in[3];
    const float* W    = (const float*)d_in[4];
    const float* b    = (const float*)d_in[5];
    float* out = (float*)d_out;

    int n = in_sizes[0] / D;     // 50000
    int E = in_sizes[1];         // 800000

    float* y;
    cudaGetSymbolAddress((void**)&y, g_y);

    // GEMM: y = x @ W^T
    const int smem_bytes = (BM * D + D * 132) * (int)sizeof(float);  // ~100 KB
    cudaFuncSetAttribute(gemm_xwT, cudaFuncAttributeMaxDynamicSharedMemorySize,
                         smem_bytes);
    int gblocks = (n + BM - 1) / BM;
    gemm_xwT<<<gblocks, GEMM_THREADS, smem_bytes>>>(x, W, y, n);

    // out = b (broadcast)
    int total4 = n * D / 4;
    init_bias<<<(total4 + 255) / 256, 256>>>(out, b, total4);

    // scatter edges: out[row] += w * y[col]
    int warps = E;
    int threads = 256;
    int blocks = (warps * 32 + threads - 1) / threads;
    edge_scatter<<<blocks, threads>>>(y, erow, ecol, ew, out, E);
}

// round 2
// speedup vs baseline: 1.4659x; 1.4659x over previous
#include <cuda_runtime.h>
#include <cuda_bf16.h>
#include <cstdint>

#define N_NODES 50000
#define D 128
#define E_MAX 800000
#define SCAN_B 512

// ---------------- device scratch (static, no allocation) -------------------
__device__ float g_y[(size_t)N_NODES * D];        // x @ W^T (25.6 MB)
__device__ int   g_cnt[N_NODES];                  // per-row edge counts
__device__ int   g_off[N_NODES + 1];              // CSR offsets
__device__ int   g_cur[N_NODES];                  // running insert cursor
__device__ int   g_tmp[N_NODES];                  // per-block-exclusive scan
__device__ int   g_bsum[(N_NODES + SCAN_B - 1) / SCAN_B];
__device__ int   g_bpre[(N_NODES + SCAN_B - 1) / SCAN_B];
__device__ int2  g_sedge[E_MAX];                  // sorted (col, w_bits)

// ---------------------------------------------------------------------------
// Kernel 1: y = x @ W^T via tf32 mma.sync m16n8k8.
// Block: 128 rows x 128 cols, 256 threads = 8 warps in 4(m) x 2(n) grid,
// warp tile 32x64. Full K=128 staged in smem (tf32-converted), pad LD=132.
// ---------------------------------------------------------------------------
__device__ __forceinline__ unsigned f2tf32(float f) {
    unsigned u;
    asm("cvt.rna.tf32.f32 %0, %1;" : "=r"(u) : "f"(f));
    return u;
}

__device__ __forceinline__ void mma_tf32(float* c, const unsigned* a,
                                         unsigned b0, unsigned b1) {
    asm volatile(
        "mma.sync.aligned.m16n8k8.row.col.f32.tf32.tf32.f32 "
        "{%0,%1,%2,%3}, {%4,%5,%6,%7}, {%8,%9}, {%0,%1,%2,%3};\n"
        : "+f"(c[0]), "+f"(c[1]), "+f"(c[2]), "+f"(c[3])
        : "r"(a[0]), "r"(a[1]), "r"(a[2]), "r"(a[3]), "r"(b0), "r"(b1));
}

#define LD 132

__global__ void gemm_tf32(const float* __restrict__ x,
                          const float* __restrict__ W,
                          float* __restrict__ y, int n) {
    extern __shared__ unsigned smem_u[];
    unsigned* As = smem_u;              // [128][LD]
    unsigned* Bs = smem_u + 128 * LD;   // [128][LD]  (W row-major: [n][k])

    int tid = threadIdx.x;
    int row0 = blockIdx.x * 128;

    // Fill W tile (tf32 bits)
    for (int i = tid; i < (D * D) / 4; i += 256) {
        int r = (i * 4) >> 7, c = (i * 4) & 127;
        float4 v = ((const float4*)W)[i];
        unsigned* p = &Bs[r * LD + c];
        p[0] = f2tf32(v.x); p[1] = f2tf32(v.y);
        p[2] = f2tf32(v.z); p[3] = f2tf32(v.w);
    }
    // Fill A tile (guarded, tf32 bits)
    for (int i = tid; i < (128 * D) / 4; i += 256) {
        int r = (i * 4) >> 7, c = (i * 4) & 127;
        int gr = row0 + r;
        float4 v = (gr < n) ? ((const float4*)(x + (size_t)gr * D))[c >> 2]
                            : make_float4(0.f, 0.f, 0.f, 0.f);
        unsigned* p = &As[r * LD + c];
        p[0] = f2tf32(v.x); p[1] = f2tf32(v.y);
        p[2] = f2tf32(v.z); p[3] = f2tf32(v.w);
    }
    __syncthreads();

    int warp = tid >> 5, lane = tid & 31;
    int wm = warp & 3, wn = warp >> 2;         // 4 x 2 warps
    int m0 = wm * 32, n0 = wn * 64;
    int grp = lane >> 2, tg = lane & 3;

    float acc[2][8][4];
    #pragma unroll
    for (int mt = 0; mt < 2; mt++)
        #pragma unroll
        for (int nt = 0; nt < 8; nt++)
            #pragma unroll
            for (int q = 0; q < 4; q++) acc[mt][nt][q] = 0.f;

    #pragma unroll
    for (int k0 = 0; k0 < D; k0 += 8) {
        unsigned a[2][4];
        #pragma unroll
        for (int mt = 0; mt < 2; mt++) {
            int r = m0 + mt * 16 + grp;
            a[mt][0] = As[r * LD + k0 + tg];
            a[mt][1] = As[(r + 8) * LD + k0 + tg];
            a[mt][2] = As[r * LD + k0 + tg + 4];
            a[mt][3] = As[(r + 8) * LD + k0 + tg + 4];
        }
        #pragma unroll
        for (int nt = 0; nt < 8; nt++) {
            int nr = n0 + nt * 8 + grp;
            unsigned b0 = Bs[nr * LD + k0 + tg];
            unsigned b1 = Bs[nr * LD + k0 + tg + 4];
            mma_tf32(acc[0][nt], a[0], b0, b1);
            mma_tf32(acc[1][nt], a[1], b0, b1);
        }
    }

    // Store D fragments: c0,c1 -> (grp, 2tg..2tg+1); c2,c3 -> (grp+8, ...)
    #pragma unroll
    for (int mt = 0; mt < 2; mt++)
        #pragma unroll
        for (int nt = 0; nt < 8; nt++) {
            int r = row0 + m0 + mt * 16 + grp;
            int c = n0 + nt * 8 + tg * 2;
            if (r < n)
                *(float2*)&y[(size_t)r * D + c] =
                    make_float2(acc[mt][nt][0], acc[mt][nt][1]);
            if (r + 8 < n)
                *(float2*)&y[(size_t)(r + 8) * D + c] =
                    make_float2(acc[mt][nt][2], acc[mt][nt][3]);
        }
}

// ---------------------------------------------------------------------------
// CSR build: zero counts -> histogram -> 3-kernel scan -> permute
// ---------------------------------------------------------------------------
__global__ void zero_cnt(int* __restrict__ cnt, int n) {
    int i = blockIdx.x * blockDim.x + threadIdx.x;
    if (i < n) cnt[i] = 0;
}

__global__ void hist(const int* __restrict__ erow, int* __restrict__ cnt, int E) {
    int e = blockIdx.x * blockDim.x + threadIdx.x;
    if (e < E) atomicAdd(&cnt[erow[e]], 1);
}

__global__ void scan1(const int* __restrict__ cnt, int* __restrict__ tmp,
                      int* __restrict__ bsum, int n) {
    __shared__ int s[SCAN_B];
    int t = threadIdx.x;
    int i = blockIdx.x * SCAN_B + t;
    int c = (i < n) ? cnt[i] : 0;
    s[t] = c;
    __syncthreads();
    #pragma unroll
    for (int o = 1; o < SCAN_B; o <<= 1) {
        int v = (t >= o) ? s[t - o] : 0;
        __syncthreads();
        s[t] += v;
        __syncthreads();
    }
    if (i < n) tmp[i] = s[t] - c;          // exclusive within block
    if (t == SCAN_B - 1) bsum[blockIdx.x] = s[t];
}

__global__ void scan2(int* __restrict__ bsum, int* __restrict__ bpre, int nb) {
    __shared__ int s[128];
    int t = threadIdx.x;
    int c = (t < nb) ? bsum[t] : 0;
    s[t] = c;
    __syncthreads();
    #pragma unroll
    for (int o = 1; o < 128; o <<= 1) {
        int v = (t >= o) ? s[t - o] : 0;
        __syncthreads();
        s[t] += v;
        __syncthreads();
    }
    if (t < nb) bpre[t] = s[t] - c;        // exclusive block prefix
}

__global__ void scan3(const int* __restrict__ tmp, const int* __restrict__ bpre,
                      int* __restrict__ off, int* __restrict__ cur,
                      int n, int E) {
    int i = blockIdx.x * blockDim.x + threadIdx.x;
    if (i < n) {
        int o = tmp[i] + bpre[i / SCAN_B];
        off[i] = o;
        cur[i] = o;
    }
    if (i == 0) off[n] = E;
}

__global__ void permute(const int* __restrict__ erow, const int* __restrict__ ecol,
                        const float* __restrict__ ew, int* __restrict__ cur,
                        int2* __restrict__ sedge, int E) {
    int e = blockIdx.x * blockDim.x + threadIdx.x;
    if (e < E) {
        int r = erow[e];
        int p = atomicAdd(&cur[r], 1);
        sedge[p] = make_int2(ecol[e], __float_as_int(ew[e]));
    }
}

// ---------------------------------------------------------------------------
// Gather: one warp per node. lane l owns floats [4l, 4l+3] of D=128.
// out[node] = b + sum_e w_e * y[col_e]   (single write, no atomics)
// ---------------------------------------------------------------------------
__global__ void gather(const float4* __restrict__ y4,
                       const int* __restrict__ off,
                       const int2* __restrict__ sedge,
                       const float* __restrict__ b,
                       float4* __restrict__ out4, int n) {
    int node = (blockIdx.x * blockDim.x + threadIdx.x) >> 5;
    int lane = threadIdx.x & 31;
    if (node >= n) return;

    int s = off[node];
    int e = off[node + 1];

    float4 acc = ((const float4*)b)[lane];

    for (int i = s; i < e; i += 32) {
        int j = i + lane;
        int2 ed = (j < e) ? sedge[j] : make_int2(0, 0);
        int cnt = min(32, e - i);
        for (int t = 0; t < cnt; t++) {
            int col = __shfl_sync(0xFFFFFFFFu, ed.x, t);
            float w = __int_as_float(__shfl_sync(0xFFFFFFFFu, ed.y, t));
            float4 v = y4[(size_t)col * 32 + lane];
            acc.x += w * v.x;
            acc.y += w * v.y;
            acc.z += w * v.z;
            acc.w += w * v.w;
        }
    }
    out4[(size_t)node * 32 + lane] = acc;
}

// ---------------------------------------------------------------------------
extern "C" void kernel_launch(void* const* d_in, const int* in_sizes, int n_in,
                              void* d_out, int out_size) {
    const float* x    = (const float*)d_in[0];
    const int*   erow = (const int*)d_in[1];
    const int*   ecol = (const int*)d_in[2];
    const float* ew   = (const float*)d_in[3];
    const float* W    = (const float*)d_in[4];
    const float* b    = (const float*)d_in[5];
    float* out = (float*)d_out;

    int n = in_sizes[0] / D;     // 50000
    int E = in_sizes[1];         // 800000

    float* y;   cudaGetSymbolAddress((void**)&y, g_y);
    int*   cnt; cudaGetSymbolAddress((void**)&cnt, g_cnt);
    int*   off; cudaGetSymbolAddress((void**)&off, g_off);
    int*   cur; cudaGetSymbolAddress((void**)&cur, g_cur);
    int*   tmp; cudaGetSymbolAddress((void**)&tmp, g_tmp);
    int*   bsum; cudaGetSymbolAddress((void**)&bsum, g_bsum);
    int*   bpre; cudaGetSymbolAddress((void**)&bpre, g_bpre);
    int2*  sedge; cudaGetSymbolAddress((void**)&sedge, g_sedge);

    // --- GEMM: y = x @ W^T (tf32 tensor cores) ---
    const int smem_bytes = 2 * 128 * LD * (int)sizeof(unsigned);  // ~135 KB
    static int attr_set = 0;
    cudaFuncSetAttribute(gemm_tf32, cudaFuncAttributeMaxDynamicSharedMemorySize,
                         smem_bytes);
    (void)attr_set;
    int gblocks = (n + 127) / 128;
    gemm_tf32<<<gblocks, 256, smem_bytes>>>(x, W, y, n);

    // --- CSR build ---
    int nb = (n + SCAN_B - 1) / SCAN_B;
    zero_cnt<<<(n + 255) / 256, 256>>>(cnt, n);
    hist<<<(E + 255) / 256, 256>>>(erow, cnt, E);
    scan1<<<nb, SCAN_B>>>(cnt, tmp, bsum, n);
    scan2<<<1, 128>>>(bsum, bpre, nb);
    scan3<<<(n + 255) / 256, 256>>>(tmp, bpre, off, cur, n, E);
    permute<<<(E + 255) / 256, 256>>>(erow, ecol, ew, cur, sedge, E);

    // --- Gather (one warp per node), fuses bias add + single store ---
    int gthreads = 256;
    int gwarps_per_block = gthreads / 32;
    int gblocks2 = (n + gwarps_per_block - 1) / gwarps_per_block;
    gather<<<gblocks2, gthreads>>>((const float4*)y, off, sedge, b,
                                   (float4*)out, n);
}

// round 5
// speedup vs baseline: 1.6164x; 1.1027x over previous
#include <cuda_runtime.h>
#include <cuda_bf16.h>
#include <cstdint>

#define N_NODES 50000
#define D 128
#define E_MAX 800000
#define SCAN_B 512

// ---------------- device scratch (static, no allocation) -------------------
__device__ float g_y[(size_t)N_NODES * D];        // x @ W^T (25.6 MB)
__device__ int   g_cnt[N_NODES];
__device__ int   g_off[N_NODES + 1];
__device__ int   g_cur[N_NODES];
__device__ int   g_tmp[N_NODES];
__device__ int   g_bsum[(N_NODES + SCAN_B - 1) / SCAN_B];
__device__ int   g_bpre[(N_NODES + SCAN_B - 1) / SCAN_B];
__device__ int2  g_sedge[E_MAX];                  // row-sorted (col, w_bits)

// ---------------------------------------------------------------------------
// Kernel 1: y = x @ W^T via tf32 mma.sync m16n8k8.
// 512 threads = 16 warps in 4(m) x 4(n); warp tile 32x32; block tile 128x128,
// full K=128 in smem (tf32 pre-converted), LD=132 (conflict-free frag reads).
// ---------------------------------------------------------------------------
__device__ __forceinline__ unsigned f2tf32(float f) {
    unsigned u;
    asm("cvt.rna.tf32.f32 %0, %1;" : "=r"(u) : "f"(f));
    return u;
}

__device__ __forceinline__ void mma_tf32(float* c, const unsigned* a,
                                         unsigned b0, unsigned b1) {
    asm volatile(
        "mma.sync.aligned.m16n8k8.row.col.f32.tf32.tf32.f32 "
        "{%0,%1,%2,%3}, {%4,%5,%6,%7}, {%8,%9}, {%0,%1,%2,%3};\n"
        : "+f"(c[0]), "+f"(c[1]), "+f"(c[2]), "+f"(c[3])
        : "r"(a[0]), "r"(a[1]), "r"(a[2]), "r"(a[3]), "r"(b0), "r"(b1));
}

#define LD 132
#define GEMM_THREADS 512

__global__ void gemm_tf32(const float* __restrict__ x,
                          const float* __restrict__ W,
                          float* __restrict__ y, int n) {
    extern __shared__ unsigned smem_u[];
    unsigned* As = smem_u;              // [128][LD]
    unsigned* Bs = smem_u + 128 * LD;   // [128][LD]  (W row-major: [n][k])

    int tid = threadIdx.x;
    int row0 = blockIdx.x * 128;

    // Fill W tile (tf32 bits)
    for (int i = tid; i < (D * D) / 4; i += GEMM_THREADS) {
        int r = (i * 4) >> 7, c = (i * 4) & 127;
        float4 v = ((const float4*)W)[i];
        unsigned* p = &Bs[r * LD + c];
        p[0] = f2tf32(v.x); p[1] = f2tf32(v.y);
        p[2] = f2tf32(v.z); p[3] = f2tf32(v.w);
    }
    // Fill A tile (guarded, tf32 bits)
    for (int i = tid; i < (128 * D) / 4; i += GEMM_THREADS) {
        int r = (i * 4) >> 7, c = (i * 4) & 127;
        int gr = row0 + r;
        float4 v = (gr < n) ? ((const float4*)(x + (size_t)gr * D))[c >> 2]
                            : make_float4(0.f, 0.f, 0.f, 0.f);
        unsigned* p = &As[r * LD + c];
        p[0] = f2tf32(v.x); p[1] = f2tf32(v.y);
        p[2] = f2tf32(v.z); p[3] = f2tf32(v.w);
    }
    __syncthreads();

    int warp = tid >> 5, lane = tid & 31;
    int wm = warp & 3, wn = warp >> 2;         // 4 x 4 warps
    int m0 = wm * 32, n0 = wn * 32;
    int grp = lane >> 2, tg = lane & 3;

    float acc[2][4][4];
    #pragma unroll
    for (int mt = 0; mt < 2; mt++)
        #pragma unroll
        for (int nt = 0; nt < 4; nt++)
            #pragma unroll
            for (int q = 0; q < 4; q++) acc[mt][nt][q] = 0.f;

    #pragma unroll
    for (int k0 = 0; k0 < D; k0 += 8) {
        unsigned a[2][4];
        #pragma unroll
        for (int mt = 0; mt < 2; mt++) {
            int r = m0 + mt * 16 + grp;
            a[mt][0] = As[r * LD + k0 + tg];
            a[mt][1] = As[(r + 8) * LD + k0 + tg];
            a[mt][2] = As[r * LD + k0 + tg + 4];
            a[mt][3] = As[(r + 8) * LD + k0 + tg + 4];
        }
        #pragma unroll
        for (int nt = 0; nt < 4; nt++) {
            int nr = n0 + nt * 8 + grp;
            unsigned b0 = Bs[nr * LD + k0 + tg];
            unsigned b1 = Bs[nr * LD + k0 + tg + 4];
            mma_tf32(acc[0][nt], a[0], b0, b1);
            mma_tf32(acc[1][nt], a[1], b0, b1);
        }
    }

    #pragma unroll
    for (int mt = 0; mt < 2; mt++)
        #pragma unroll
        for (int nt = 0; nt < 4; nt++) {
            int r = row0 + m0 + mt * 16 + grp;
            int c = n0 + nt * 8 + tg * 2;
            if (r < n)
                *(float2*)&y[(size_t)r * D + c] =
                    make_float2(acc[mt][nt][0], acc[mt][nt][1]);
            if (r + 8 < n)
                *(float2*)&y[(size_t)(r + 8) * D + c] =
                    make_float2(acc[mt][nt][2], acc[mt][nt][3]);
        }
}

// ---------------------------------------------------------------------------
// CSR build: zero -> histogram -> shuffle-scan (3 kernels) -> permute
// ---------------------------------------------------------------------------
__global__ void zero_cnt(int* __restrict__ cnt, int n) {
    int i = blockIdx.x * blockDim.x + threadIdx.x;
    if (i < n) cnt[i] = 0;
}

__global__ void hist(const int* __restrict__ erow, int* __restrict__ cnt, int E) {
    int e = blockIdx.x * blockDim.x + threadIdx.x;
    if (e < E) atomicAdd(&cnt[erow[e]], 1);
}

__device__ __forceinline__ int warp_incl_scan(int v, int lane) {
    #pragma unroll
    for (int o = 1; o < 32; o <<= 1) {
        int u = __shfl_up_sync(0xFFFFFFFFu, v, o);
        if (lane >= o) v += u;
    }
    return v;
}

// Block 512 = 16 warps; per-block exclusive scan + block total.
__global__ void scan1(const int* __restrict__ cnt, int* __restrict__ tmp,
                      int* __restrict__ bsum, int n) {
    __shared__ int ws[16];
    int t = threadIdx.x;
    int lane = t & 31, wid = t >> 5;
    int i = blockIdx.x * SCAN_B + t;
    int c = (i < n) ? cnt[i] : 0;

    int v = warp_incl_scan(c, lane);            // inclusive within warp
    if (lane == 31) ws[wid] = v;
    __syncthreads();
    if (wid == 0) {
        int s = (lane < 16) ? ws[lane] : 0;
        s = warp_incl_scan(s, lane);
        if (lane < 16) ws[lane] = s;
    }
    __syncthreads();
    int wpre = (wid > 0) ? ws[wid - 1] : 0;     // exclusive warp prefix
    if (i < n) tmp[i] = wpre + v - c;           // block-exclusive
    if (t == SCAN_B - 1) bsum[blockIdx.x] = wpre + v;
}

// Single block of 128 scans nb (<=128) block sums -> exclusive prefixes.
__global__ void scan2(const int* __restrict__ bsum, int* __restrict__ bpre,
                      int nb) {
    __shared__ int ws[4];
    int t = threadIdx.x;
    int lane = t & 31, wid = t >> 5;
    int c = (t < nb) ? bsum[t] : 0;
    int v = warp_incl_scan(c, lane);
    if (lane == 31) ws[wid] = v;
    __syncthreads();
    if (t == 0) {
        int s = 0;
        #pragma unroll
        for (int w = 0; w < 4; w++) { int u = ws[w]; ws[w] = s; s += u; }
    }
    __syncthreads();
    if (t < nb) bpre[t] = ws[wid] + v - c;
}

__global__ void scan3(const int* __restrict__ tmp, const int* __restrict__ bpre,
                      int* __restrict__ off, int* __restrict__ cur,
                      int n, int E) {
    int i = blockIdx.x * blockDim.x + threadIdx.x;
    if (i < n) {
        int o = tmp[i] + bpre[i / SCAN_B];
        off[i] = o;
        cur[i] = o;
    }
    if (i == 0) off[n] = E;
}

__global__ void permute(const int* __restrict__ erow, const int* __restrict__ ecol,
                        const float* __restrict__ ew, int* __restrict__ cur,
                        int2* __restrict__ sedge, int E) {
    int e = blockIdx.x * blockDim.x + threadIdx.x;
    if (e < E) {
        int r = erow[e];
        int p = atomicAdd(&cur[r], 1);
        sedge[p] = make_int2(ecol[e], __float_as_int(ew[e]));
    }
}

// ---------------------------------------------------------------------------
// Gather: one warp per node; lane l owns floats [4l,4l+3].
// out[node] = b + sum_e w_e * y[col_e]   (single write, no atomics)
// ---------------------------------------------------------------------------
__global__ void gather(const float4* __restrict__ y4,
                       const int* __restrict__ off,
                       const int2* __restrict__ sedge,
                       const float* __restrict__ b,
                       float4* __restrict__ out4, int n) {
    int node = (blockIdx.x * blockDim.x + threadIdx.x) >> 5;
    int lane = threadIdx.x & 31;
    if (node >= n) return;

    int s = off[node];
    int e = off[node + 1];

    float4 acc = ((const float4*)b)[lane];

    for (int i = s; i < e; i += 32) {
        int j = i + lane;
        int2 ed = (j < e) ? sedge[j] : make_int2(0, 0);
        int cnt = min(32, e - i);
        #pragma unroll 4
        for (int t = 0; t < cnt; t++) {
            int col = __shfl_sync(0xFFFFFFFFu, ed.x, t);
            float w = __int_as_float(__shfl_sync(0xFFFFFFFFu, ed.y, t));
            float4 v = y4[(size_t)col * 32 + lane];
            acc.x += w * v.x;
            acc.y += w * v.y;
            acc.z += w * v.z;
            acc.w += w * v.w;
        }
    }
    out4[(size_t)node * 32 + lane] = acc;
}

// ---------------------------------------------------------------------------
extern "C" void kernel_launch(void* const* d_in, const int* in_sizes, int n_in,
                              void* d_out, int out_size) {
    const float* x    = (const float*)d_in[0];
    const int*   erow = (const int*)d_in[1];
    const int*   ecol = (const int*)d_in[2];
    const float* ew   = (const float*)d_in[3];
    const float* W    = (const float*)d_in[4];
    const float* b    = (const float*)d_in[5];
    float* out = (float*)d_out;

    int n = in_sizes[0] / D;     // 50000
    int E = in_sizes[1];         // 800000

    float* y;    cudaGetSymbolAddress((void**)&y, g_y);
    int*   cnt;  cudaGetSymbolAddress((void**)&cnt, g_cnt);
    int*   off;  cudaGetSymbolAddress((void**)&off, g_off);
    int*   cur;  cudaGetSymbolAddress((void**)&cur, g_cur);
    int*   tmp;  cudaGetSymbolAddress((void**)&tmp, g_tmp);
    int*   bsum; cudaGetSymbolAddress((void**)&bsum, g_bsum);
    int*   bpre; cudaGetSymbolAddress((void**)&bpre, g_bpre);
    int2*  sedge; cudaGetSymbolAddress((void**)&sedge, g_sedge);

    // --- GEMM: y = x @ W^T (tf32 tensor cores, 512 threads/block) ---
    const int smem_bytes = 2 * 128 * LD * (int)sizeof(unsigned);  // ~135 KB
    cudaFuncSetAttribute(gemm_tf32, cudaFuncAttributeMaxDynamicSharedMemorySize,
                         smem_bytes);
    int gblocks = (n + 127) / 128;
    gemm_tf32<<<gblocks, GEMM_THREADS, smem_bytes>>>(x, W, y, n);

    // --- CSR build ---
    int nb = (n + SCAN_B - 1) / SCAN_B;
    zero_cnt<<<(n + 511) / 512, 512>>>(cnt, n);
    hist<<<(E + 511) / 512, 512>>>(erow, cnt, E);
    scan1<<<nb, SCAN_B>>>(cnt, tmp, bsum, n);
    scan2<<<1, 128>>>(bsum, bpre, nb);
    scan3<<<(n + 511) / 512, 512>>>(tmp, bpre, off, cur, n, E);
    permute<<<(E + 511) / 512, 512>>>(erow, ecol, ew, cur, sedge, E);

    // --- Gather (one warp per node), fused bias + single store ---
    int gthreads = 512;
    int gwpb = gthreads / 32;
    int gblocks2 = (n + gwpb - 1) / gwpb;
    gather<<<gblocks2, gthreads>>>((const float4*)y, off, sedge, b,
                                   (float4*)out, n);
}